// round 3
// baseline (speedup 1.0000x reference)
#include <cuda_runtime.h>
#include <cstdint>

#define BB 8
#define C_IN 64
#define C_OUT 128
#define HH 256
#define WW 256
#define NK 8

#define TH 16
#define TW 64
#define COT 16          // c_out per block (8 warps x 2 each)
#define SROW 68         // padded smem row stride (floats, even)

__device__ float g_pooled[BB * C_IN];
__device__ float g_attn[BB * NK];
__device__ float g_mixed[BB * C_OUT * C_IN * 9];

typedef unsigned long long ull;

__device__ __forceinline__ ull pk(float lo, float hi) {
    ull r;
    asm("mov.b64 %0, {%1, %2};" : "=l"(r) : "f"(lo), "f"(hi));
    return r;
}
__device__ __forceinline__ void upk(float& lo, float& hi, ull v) {
    asm("mov.b64 {%0, %1}, %2;" : "=f"(lo), "=f"(hi) : "l"(v));
}
__device__ __forceinline__ ull ffma2(ull a, ull b, ull c) {
    ull d;
    asm("fma.rn.f32x2 %0, %1, %2, %3;" : "=l"(d) : "l"(a), "l"(b), "l"(c));
    return d;
}
__device__ __forceinline__ void cpasync4(uint32_t saddr, const void* g, int src_sz) {
    asm volatile("cp.async.ca.shared.global [%0], [%1], 4, %2;"
                 :: "r"(saddr), "l"(g), "r"(src_sz));
}
__device__ __forceinline__ void cp_commit() {
    asm volatile("cp.async.commit_group;");
}
__device__ __forceinline__ void cp_wait1() {
    asm volatile("cp.async.wait_group 1;");
}

// ---------------- Kernel 1: global average pool per (b, c_in) ----------------
__global__ void pool_kernel(const float* __restrict__ x) {
    int idx = blockIdx.x;  // b*C_IN + ci
    const float4* p = reinterpret_cast<const float4*>(x + (size_t)idx * (HH * WW));
    float s = 0.f;
    for (int i = threadIdx.x; i < (HH * WW) / 4; i += blockDim.x) {
        float4 v = p[i];
        s += v.x + v.y + v.z + v.w;
    }
    __shared__ float red[256];
    red[threadIdx.x] = s;
    __syncthreads();
    for (int off = 128; off > 0; off >>= 1) {
        if (threadIdx.x < off) red[threadIdx.x] += red[threadIdx.x + off];
        __syncthreads();
    }
    if (threadIdx.x == 0) g_pooled[idx] = red[0] * (1.0f / (HH * WW));
}

// ---------------- Kernel 2: logits + softmax -> attention weights ----------------
__global__ void attn_kernel(const float* __restrict__ attn_w,
                            const float* __restrict__ attn_b) {
    __shared__ float lg[BB * NK];
    int t = threadIdx.x;
    if (t < BB * NK) {
        int b = t / NK, n = t % NK;
        float s = attn_b[n];
        #pragma unroll 8
        for (int c = 0; c < C_IN; c++) s += g_pooled[b * C_IN + c] * attn_w[n * C_IN + c];
        lg[t] = s;
    }
    __syncthreads();
    if (t < BB) {
        float m = -1e30f;
        for (int n = 0; n < NK; n++) m = fmaxf(m, lg[t * NK + n]);
        float e[NK];
        float sum = 0.f;
        for (int n = 0; n < NK; n++) { e[n] = expf(lg[t * NK + n] - m); sum += e[n]; }
        float inv = 1.0f / sum;
        for (int n = 0; n < NK; n++) g_attn[t * NK + n] = e[n] * inv;
    }
}

// ---------------- Kernel 3: mix kernel bank by attention ----------------
__global__ void mix_kernel(const float* __restrict__ bank) {
    const int R = C_OUT * C_IN * 9;
    int i = blockIdx.x * blockDim.x + threadIdx.x;
    if (i >= BB * R) return;
    int b = i / R, r = i - b * R;
    float s = 0.f;
    #pragma unroll
    for (int n = 0; n < NK; n++) s += g_attn[b * NK + n] * bank[(size_t)n * R + r];
    g_mixed[i] = s;
}

// ---------------- Kernel 4: conv, f32x2 FMA + LDS.64 + cp.async pipeline ----------
// Block: 256 threads = 8 warps. Tile: 64 wide x 16 tall, 16 c_out.
// Warp w handles c_out {cobase+w, cobase+8+w}. Lane covers adjacent output
// columns (2l, 2l+1), packed into one f32x2. Per smem row: 2x LDS.64 gives
// inputs cols 2l-1..2l+2; one register recombine forms the middle pair.
// 2-stage cp.async ping-pong prefetches tile+weights of ci+1 during compute.
__global__ void __launch_bounds__(256, 2) conv_kernel(const float* __restrict__ x,
                                                      float* __restrict__ out) {
    __shared__ float sx[2][TH + 2][SROW];
    __shared__ float swt[2][COT][9];

    int tid = threadIdx.x;
    int lane = tid & 31;
    int wrp = tid >> 5;
    int gx0 = blockIdx.x * TW;
    int gy0 = blockIdx.y * TH;
    int bz = blockIdx.z;               // b * (C_OUT/COT) + cog
    int b = bz >> 3;                   // C_OUT/COT = 8
    int cobase = (bz & 7) * COT;

    ull accA[TH], accB[TH];
    #pragma unroll
    for (int i = 0; i < TH; i++) { accA[i] = 0ULL; accB[i] = 0ULL; }

    const float* xb = x + (size_t)b * C_IN * (HH * WW);
    const float* wb = g_mixed + (((size_t)b * C_OUT + cobase) * C_IN) * 9;

    uint32_t sx_base = (uint32_t)__cvta_generic_to_shared(&sx[0][0][0]);
    uint32_t sw_base = (uint32_t)__cvta_generic_to_shared(&swt[0][0][0]);

    // Prefetch issue for channel ci into buffer buf.
    auto prefetch = [&](int ci, int buf) {
        const float* xp = xb + (size_t)ci * (HH * WW);
        uint32_t sbase = sx_base + (uint32_t)buf * ((TH + 2) * SROW * 4);
        #pragma unroll
        for (int i = tid; i < (TH + 2) * 66; i += 256) {
            int r = i / 66;
            int c = i - r * 66;
            int y = gy0 + r - 1;
            int xc = gx0 + c - 1;
            bool ok = (y >= 0) & (y < HH) & (xc >= 0) & (xc < WW);
            const float* src = xp + (ok ? (y * WW + xc) : 0);
            cpasync4(sbase + (uint32_t)(r * SROW + c) * 4, src, ok ? 4 : 0);
        }
        if (tid < COT * 9) {
            int col = tid / 9, t = tid - col * 9;
            const float* src = wb + ((size_t)col * C_IN + ci) * 9 + t;
            cpasync4(sw_base + (uint32_t)(buf * COT * 9 + tid) * 4, src, 4);
        }
    };

    prefetch(0, 0);
    cp_commit();

    for (int ci = 0; ci < C_IN; ci++) {
        int cur = ci & 1;
        if (ci + 1 < C_IN) prefetch(ci + 1, cur ^ 1);
        cp_commit();
        cp_wait1();          // buffer `cur` (group for ci) complete
        __syncthreads();

        // packed weights (w, w) for both c_outs of this warp
        ull wA[9], wB[9];
        #pragma unroll
        for (int t = 0; t < 9; t++) {
            float a = swt[cur][wrp][t];
            float c2 = swt[cur][wrp + 8][t];
            wA[t] = pk(a, a);
            wB[t] = pk(c2, c2);
        }

        #pragma unroll
        for (int r = 0; r < TH + 2; r++) {
            float2 q0 = *reinterpret_cast<const float2*>(&sx[cur][r][2 * lane]);
            float2 q1 = *reinterpret_cast<const float2*>(&sx[cur][r][2 * lane + 2]);
            ull p0 = pk(q0.x, q0.y);     // inputs cols 2l-1, 2l   (kw=0)
            ull p1 = pk(q0.y, q1.x);     // inputs cols 2l,   2l+1 (kw=1)
            ull p2 = pk(q1.x, q1.y);     // inputs cols 2l+1, 2l+2 (kw=2)
            if (r < TH) {  // kh = 0 for output row r
                accA[r] = ffma2(p0, wA[0], ffma2(p1, wA[1], ffma2(p2, wA[2], accA[r])));
                accB[r] = ffma2(p0, wB[0], ffma2(p1, wB[1], ffma2(p2, wB[2], accB[r])));
            }
            if (r >= 1 && r - 1 < TH) {  // kh = 1 for output row r-1
                accA[r-1] = ffma2(p0, wA[3], ffma2(p1, wA[4], ffma2(p2, wA[5], accA[r-1])));
                accB[r-1] = ffma2(p0, wB[3], ffma2(p1, wB[4], ffma2(p2, wB[5], accB[r-1])));
            }
            if (r >= 2) {  // kh = 2 for output row r-2
                accA[r-2] = ffma2(p0, wA[6], ffma2(p1, wA[7], ffma2(p2, wA[8], accA[r-2])));
                accB[r-2] = ffma2(p0, wB[6], ffma2(p1, wB[7], ffma2(p2, wB[8], accB[r-2])));
            }
        }
        __syncthreads();   // before any warp overwrites buffer `cur` (at ci+2 prefetch)
    }

    int co0 = cobase + wrp;
    int co1 = cobase + 8 + wrp;
    float* opA = out + (((size_t)b * C_OUT + co0) * HH + gy0) * WW + gx0 + 2 * lane;
    float* opB = out + (((size_t)b * C_OUT + co1) * HH + gy0) * WW + gx0 + 2 * lane;
    #pragma unroll
    for (int o = 0; o < TH; o++) {
        float lo, hi;
        upk(lo, hi, accA[o]);
        *reinterpret_cast<float2*>(&opA[o * WW]) = make_float2(lo, hi);
        upk(lo, hi, accB[o]);
        *reinterpret_cast<float2*>(&opB[o * WW]) = make_float2(lo, hi);
    }
}

extern "C" void kernel_launch(void* const* d_in, const int* in_sizes, int n_in,
                              void* d_out, int out_size) {
    const float* x    = (const float*)d_in[0];
    const float* bank = (const float*)d_in[1];
    const float* aw   = (const float*)d_in[2];
    const float* ab   = (const float*)d_in[3];
    float* out = (float*)d_out;

    pool_kernel<<<BB * C_IN, 256>>>(x);
    attn_kernel<<<1, 64>>>(aw, ab);
    mix_kernel<<<(BB * C_OUT * C_IN * 9 + 255) / 256, 256>>>(bank);

    dim3 g(WW / TW, HH / TH, BB * (C_OUT / COT));
    conv_kernel<<<g, 256>>>(x, out);
}